// round 3
// baseline (speedup 1.0000x reference)
#include <cuda_runtime.h>
#include <math.h>

#define NN 100000
#define NF 16
#define C1 128
#define C2 256
#define MAXE 800000
#define EPSV 1e-5f

// ---------------- scratch ----------------
__device__ float g_aggx[NN * NF];
__device__ float g_h1[NN * C1];
__device__ float g_agg1[NN * C1];
__device__ float g_h2pre[NN * C2];
__device__ float g_u[NN * C1];
__device__ float g_v[NN * C1];
__device__ float g_stats1[2 * C1];
__device__ float g_stats2[2 * C2];
__device__ float g_bnA[C2];
__device__ float g_bnB[C2];
__device__ int g_cnt[NN];
__device__ int g_off[NN];
__device__ int g_cur[NN];
__device__ int g_csr[MAXE];

// ---------------- helpers ----------------
__device__ __forceinline__ float lrelu(float y) { return y > 0.f ? y : 0.01f * y; }
__device__ __forceinline__ unsigned tf32r(float x) {
    unsigned r; asm("cvt.rna.tf32.f32 %0, %1;" : "=r"(r) : "f"(x)); return r;
}
__device__ __forceinline__ void mma8(float4& d, const unsigned a[4], unsigned b0, unsigned b1) {
    asm volatile("mma.sync.aligned.m16n8k8.row.col.f32.tf32.tf32.f32 "
                 "{%0,%1,%2,%3},{%4,%5,%6,%7},{%8,%9},{%0,%1,%2,%3};"
                 : "+f"(d.x), "+f"(d.y), "+f"(d.z), "+f"(d.w)
                 : "r"(a[0]), "r"(a[1]), "r"(a[2]), "r"(a[3]), "r"(b0), "r"(b1));
}

// ---------------- K0: zero counts + stats ----------------
__global__ void k_zero(int n) {
    int i = blockIdx.x * blockDim.x + threadIdx.x;
    if (i < n) g_cnt[i] = 0;
    if (i < 2 * C1) g_stats1[i] = 0.f;
    if (i < 2 * C2) g_stats2[i] = 0.f;
}

// ---------------- K1: histogram of dst ----------------
__global__ void k_hist(const int* __restrict__ dst, int E) {
    int e = blockIdx.x * blockDim.x + threadIdx.x;
    if (e < E) atomicAdd(&g_cnt[dst[e]], 1);
}

// ---------------- K2: single-block exclusive scan -> g_off, g_cur ----------------
__global__ __launch_bounds__(1024) void k_scan(int n) {
    __shared__ int bs[1024];
    int t = threadIdx.x;
    const int CH = (NN + 1023) / 1024;  // 98
    int base = t * CH;
    int s = 0;
    for (int i = 0; i < CH; i++) {
        int idx = base + i;
        if (idx < n) s += g_cnt[idx];
    }
    bs[t] = s;
    __syncthreads();
    for (int off = 1; off < 1024; off <<= 1) {
        int v = (t >= off) ? bs[t - off] : 0;
        __syncthreads();
        bs[t] += v;
        __syncthreads();
    }
    int pre = (t > 0) ? bs[t - 1] : 0;
    for (int i = 0; i < CH; i++) {
        int idx = base + i;
        if (idx < n) {
            int c = g_cnt[idx];
            g_off[idx] = pre;
            g_cur[idx] = pre;
            pre += c;
        }
    }
}

// ---------------- K3: scatter edge srcs into CSR ----------------
__global__ void k_csr(const int* __restrict__ src, const int* __restrict__ dst, int E) {
    int e = blockIdx.x * blockDim.x + threadIdx.x;
    if (e >= E) return;
    int pos = atomicAdd(&g_cur[dst[e]], 1);
    g_csr[pos] = src[e];
}

// ---------------- K4: aggx = mean over neighbors+self of x  (4 lanes/node) ----------------
__global__ void k_aggx(const float* __restrict__ x, int n) {
    int tid = blockIdx.x * blockDim.x + threadIdx.x;
    int node = tid >> 2;
    if (node >= n) return;
    int sub = tid & 3;
    int cnt = g_cnt[node], off = g_off[node];
    const float4* xp = (const float4*)x;
    float4 acc = xp[(size_t)node * 4 + sub];
    for (int i = 0; i < cnt; i++) {
        int s = g_csr[off + i];
        float4 v = xp[(size_t)s * 4 + sub];
        acc.x += v.x; acc.y += v.y; acc.z += v.z; acc.w += v.w;
    }
    float r = 1.f / (float)(cnt + 1);
    acc.x *= r; acc.y *= r; acc.z *= r; acc.w *= r;
    ((float4*)g_aggx)[(size_t)node * 4 + sub] = acc;
}

// ---------------- K5: h1pre = aggx @ W1 + b1, BN1 stats (weights in regs) ----------------
__global__ __launch_bounds__(256) void k_gcn1(const float* __restrict__ W1,
                                              const float* __restrict__ b1, int n) {
    __shared__ float4 xs[64 * 4];
    int t = threadIdx.x;
    int c = t & 127, half = t >> 7;
    float w[16];
    #pragma unroll
    for (int k = 0; k < 16; k++) w[k] = W1[k * C1 + c];
    int n0 = blockIdx.x * 64;
    for (int i = t; i < 256; i += 256) {
        int nn = n0 + (i >> 2);
        xs[i] = (nn < n) ? ((const float4*)g_aggx)[(size_t)nn * 4 + (i & 3)]
                         : make_float4(0.f, 0.f, 0.f, 0.f);
    }
    __syncthreads();
    float bc = b1[c];
    float s = 0.f, q = 0.f;
    for (int j = half * 32; j < half * 32 + 32; j++) {
        int nn = n0 + j;
        if (nn >= n) break;
        float4 x0 = xs[j * 4], x1 = xs[j * 4 + 1], x2 = xs[j * 4 + 2], x3 = xs[j * 4 + 3];
        float acc = bc;
        acc = fmaf(x0.x, w[0], acc);  acc = fmaf(x0.y, w[1], acc);
        acc = fmaf(x0.z, w[2], acc);  acc = fmaf(x0.w, w[3], acc);
        acc = fmaf(x1.x, w[4], acc);  acc = fmaf(x1.y, w[5], acc);
        acc = fmaf(x1.z, w[6], acc);  acc = fmaf(x1.w, w[7], acc);
        acc = fmaf(x2.x, w[8], acc);  acc = fmaf(x2.y, w[9], acc);
        acc = fmaf(x2.z, w[10], acc); acc = fmaf(x2.w, w[11], acc);
        acc = fmaf(x3.x, w[12], acc); acc = fmaf(x3.y, w[13], acc);
        acc = fmaf(x3.z, w[14], acc); acc = fmaf(x3.w, w[15], acc);
        g_h1[(size_t)nn * C1 + c] = acc;
        s += acc; q += acc * acc;
    }
    atomicAdd(&g_stats1[c], s);
    atomicAdd(&g_stats1[C1 + c], q);
}

// ---------------- K6: BN1 + leaky relu -> h1 ----------------
__global__ void k_bn1(const float* __restrict__ gamma, const float* __restrict__ beta,
                      float nf, int n) {
    int i = blockIdx.x * blockDim.x + threadIdx.x;
    int tot = n * (C1 / 4);
    if (i >= tot) return;
    int cb = (i & (C1 / 4 - 1)) * 4;
    float4 h = ((const float4*)g_h1)[i];
    float hv[4] = {h.x, h.y, h.z, h.w};
    float o[4];
    #pragma unroll
    for (int c = 0; c < 4; c++) {
        float mu = g_stats1[cb + c] / nf;
        float var = g_stats1[C1 + cb + c] / nf - mu * mu;
        float sc = gamma[cb + c] * rsqrtf(var + EPSV);
        o[c] = lrelu(fmaf(sc, hv[c] - mu, beta[cb + c]));
    }
    ((float4*)g_h1)[i] = make_float4(o[0], o[1], o[2], o[3]);
}

// ---------------- K7: agg1 = mean over neighbors+self of h1  (warp/node) ----------------
__global__ void k_agg1(int n) {
    int tid = blockIdx.x * blockDim.x + threadIdx.x;
    int node = tid >> 5;
    if (node >= n) return;
    int lane = tid & 31;
    int cnt = g_cnt[node], off = g_off[node];
    const float4* hp = (const float4*)g_h1;
    float4 acc = hp[(size_t)node * 32 + lane];
    for (int i = 0; i < cnt; i++) {
        int s = g_csr[off + i];
        float4 v = hp[(size_t)s * 32 + lane];
        acc.x += v.x; acc.y += v.y; acc.z += v.z; acc.w += v.w;
    }
    float r = 1.f / (float)(cnt + 1);
    acc.x *= r; acc.y *= r; acc.z *= r; acc.w *= r;
    ((float4*)g_agg1)[(size_t)node * 32 + lane] = acc;
}

// ---------------- K8: h2pre = agg1 @ W2 + b2 (tf32) ----------------
#define AST 36
#define BST 264
__global__ __launch_bounds__(256) void k_gcn2(const float* __restrict__ W2,
                                              const float* __restrict__ b2, int n) {
    __shared__ unsigned As[64 * AST];
    __shared__ unsigned Bs[32 * BST];
    int t = threadIdx.x;
    int lane = t & 31, warp = t >> 5;
    int wr = warp >> 1, wc = warp & 1;
    int n0 = blockIdx.x * 64;
    float4 acc[16];
    #pragma unroll
    for (int j = 0; j < 16; j++) acc[j] = make_float4(0.f, 0.f, 0.f, 0.f);
    for (int kk = 0; kk < C1; kk += 32) {
        __syncthreads();
        for (int i = t; i < 64 * 32; i += 256) {
            int r = i >> 5, k = i & 31;
            int nn = n0 + r;
            float vv = (nn < n) ? g_agg1[(size_t)nn * C1 + kk + k] : 0.f;
            As[r * AST + k] = tf32r(vv);
        }
        for (int i = t; i < 32 * 256; i += 256) {
            int k = i >> 8, c = i & 255;
            Bs[k * BST + c] = tf32r(W2[(size_t)(kk + k) * C2 + c]);
        }
        __syncthreads();
        #pragma unroll
        for (int ks = 0; ks < 4; ks++) {
            int k0 = ks * 8;
            unsigned a[4];
            int r0 = wr * 16 + (lane >> 2);
            a[0] = As[r0 * AST + k0 + (lane & 3)];
            a[1] = As[(r0 + 8) * AST + k0 + (lane & 3)];
            a[2] = As[r0 * AST + k0 + 4 + (lane & 3)];
            a[3] = As[(r0 + 8) * AST + k0 + 4 + (lane & 3)];
            #pragma unroll
            for (int j = 0; j < 16; j++) {
                int nn0 = wc * 128 + 8 * j;
                unsigned b0 = Bs[(k0 + (lane & 3)) * BST + nn0 + (lane >> 2)];
                unsigned b1 = Bs[(k0 + 4 + (lane & 3)) * BST + nn0 + (lane >> 2)];
                mma8(acc[j], a, b0, b1);
            }
        }
    }
    int r0 = n0 + wr * 16 + (lane >> 2);
    #pragma unroll
    for (int j = 0; j < 16; j++) {
        int c0 = wc * 128 + 8 * j + 2 * (lane & 3);
        float2 bb = make_float2(b2[c0], b2[c0 + 1]);
        if (r0 < n)
            *(float2*)&g_h2pre[(size_t)r0 * C2 + c0] =
                make_float2(acc[j].x + bb.x, acc[j].y + bb.y);
        if (r0 + 8 < n)
            *(float2*)&g_h2pre[(size_t)(r0 + 8) * C2 + c0] =
                make_float2(acc[j].z + bb.x, acc[j].w + bb.y);
    }
}

// ---------------- K9: BN2 stats ----------------
__global__ __launch_bounds__(256) void k_stats2(int n) {
    int col = threadIdx.x;
    int r0 = blockIdx.x * 256;
    int r1 = min(r0 + 256, n);
    float s = 0.f, q = 0.f;
    for (int r = r0; r < r1; r++) {
        float h = g_h2pre[(size_t)r * C2 + col];
        s += h; q += h * h;
    }
    atomicAdd(&g_stats2[col], s);
    atomicAdd(&g_stats2[C2 + col], q);
}

// ---------------- K10: BN2 affine params ----------------
__global__ void k_bnp2(const float* __restrict__ gamma, const float* __restrict__ beta, float nf) {
    int c = threadIdx.x;
    float mu = g_stats2[c] / nf;
    float var = g_stats2[C2 + c] / nf - mu * mu;
    float a = gamma[c] * rsqrtf(var + EPSV);
    g_bnA[c] = a;
    g_bnB[c] = beta[c] - a * mu;
}

// ---------------- K11: fused BN2+lrelu -> h2 (out) and u/v GEMM (tf32) ----------------
__global__ __launch_bounds__(256) void k_uv(float* __restrict__ h2out,
                                            const float* __restrict__ Wp1,
                                            const float* __restrict__ bp1, int n) {
    __shared__ unsigned As[64 * AST];
    __shared__ unsigned Bs[32 * BST];
    __shared__ float bnA[C2], bnB[C2];
    int t = threadIdx.x;
    int lane = t & 31, warp = t >> 5;
    int wr = warp >> 1, wc = warp & 1;
    int n0 = blockIdx.x * 64;
    if (t < 256) { bnA[t] = g_bnA[t]; bnB[t] = g_bnB[t]; }
    float4 acc[16];
    #pragma unroll
    for (int j = 0; j < 16; j++) acc[j] = make_float4(0.f, 0.f, 0.f, 0.f);
    for (int kk = 0; kk < C2; kk += 32) {
        __syncthreads();
        for (int i = t; i < 64 * 32; i += 256) {
            int r = i >> 5, k = i & 31;
            int nn = n0 + r;
            float vv = 0.f;
            if (nn < n) {
                float hp = g_h2pre[(size_t)nn * C2 + kk + k];
                vv = lrelu(fmaf(bnA[kk + k], hp, bnB[kk + k]));
                h2out[(size_t)nn * C2 + kk + k] = vv;
            }
            As[r * AST + k] = tf32r(vv);
        }
        for (int i = t; i < 32 * 256; i += 256) {
            int k = i >> 8, c = i & 255;
            float vv = (c < 128) ? Wp1[(size_t)(kk + k) * 128 + c]
                                 : Wp1[(size_t)(256 + kk + k) * 128 + (c - 128)];
            Bs[k * BST + c] = tf32r(vv);
        }
        __syncthreads();
        #pragma unroll
        for (int ks = 0; ks < 4; ks++) {
            int k0 = ks * 8;
            unsigned a[4];
            int r0 = wr * 16 + (lane >> 2);
            a[0] = As[r0 * AST + k0 + (lane & 3)];
            a[1] = As[(r0 + 8) * AST + k0 + (lane & 3)];
            a[2] = As[r0 * AST + k0 + 4 + (lane & 3)];
            a[3] = As[(r0 + 8) * AST + k0 + 4 + (lane & 3)];
            #pragma unroll
            for (int j = 0; j < 16; j++) {
                int nn0 = wc * 128 + 8 * j;
                unsigned b0 = Bs[(k0 + (lane & 3)) * BST + nn0 + (lane >> 2)];
                unsigned b1 = Bs[(k0 + 4 + (lane & 3)) * BST + nn0 + (lane >> 2)];
                mma8(acc[j], a, b0, b1);
            }
        }
    }
    int r0 = n0 + wr * 16 + (lane >> 2);
    #pragma unroll
    for (int j = 0; j < 16; j++) {
        int c0 = wc * 128 + 8 * j + 2 * (lane & 3);
        if (wc == 0) {
            float2 bb = make_float2(bp1[c0], bp1[c0 + 1]);
            if (r0 < n)
                *(float2*)&g_u[(size_t)r0 * C1 + c0] =
                    make_float2(acc[j].x + bb.x, acc[j].y + bb.y);
            if (r0 + 8 < n)
                *(float2*)&g_u[(size_t)(r0 + 8) * C1 + c0] =
                    make_float2(acc[j].z + bb.x, acc[j].w + bb.y);
        } else {
            int cv = c0 - 128;
            if (r0 < n)
                *(float2*)&g_v[(size_t)r0 * C1 + cv] = make_float2(acc[j].x, acc[j].y);
            if (r0 + 8 < n)
                *(float2*)&g_v[(size_t)(r0 + 8) * C1 + cv] = make_float2(acc[j].z, acc[j].w);
        }
    }
}

// ---------------- K12: per-edge MLP (tf32) ----------------
#define EAST 132
#define EWST 72
#define EPST 66
__global__ __launch_bounds__(256) void k_edge(const int* __restrict__ src, const int* __restrict__ dst,
                                              const float* __restrict__ Wp2, const float* __restrict__ bp2,
                                              const float* __restrict__ Wp3, const float* __restrict__ bp3,
                                              float* __restrict__ pred, int E) {
    extern __shared__ unsigned smx[];
    unsigned* As = smx;
    unsigned* Ws = smx + 128 * EAST;
    float* w3s = (float*)(Ws + 128 * EWST);
    float* bp2s = w3s + 64;
    int t = threadIdx.x;
    int lane = t & 31, warp = t >> 5;
    int e0 = blockIdx.x * 128;

    {
        int el = t >> 1, half = t & 1;
        int e = e0 + el;
        unsigned* row = As + el * EAST + 64 * half;
        if (e < E) {
            int s = src[e], d = dst[e];
            const float4* up = (const float4*)(g_u + (size_t)s * C1 + 64 * half);
            const float4* vp = (const float4*)(g_v + (size_t)d * C1 + 64 * half);
            #pragma unroll
            for (int i = 0; i < 16; i++) {
                float4 uu = up[i], vv = vp[i];
                float a0 = uu.x + vv.x, a1 = uu.y + vv.y;
                float a2 = uu.z + vv.z, a3 = uu.w + vv.w;
                row[4 * i + 0] = tf32r(a0 > 0.f ? a0 : 0.f);
                row[4 * i + 1] = tf32r(a1 > 0.f ? a1 : 0.f);
                row[4 * i + 2] = tf32r(a2 > 0.f ? a2 : 0.f);
                row[4 * i + 3] = tf32r(a3 > 0.f ? a3 : 0.f);
            }
        } else {
            #pragma unroll
            for (int i = 0; i < 64; i++) row[i] = 0u;
        }
    }
    for (int i = t; i < 128 * 64; i += 256) {
        int k = i >> 6, c = i & 63;
        Ws[k * EWST + c] = tf32r(Wp2[i]);
    }
    if (t < 64) { w3s[t] = Wp3[t]; bp2s[t] = bp2[t]; }
    __syncthreads();

    float4 acc[8];
    #pragma unroll
    for (int j = 0; j < 8; j++) acc[j] = make_float4(0.f, 0.f, 0.f, 0.f);
    int r0 = warp * 16 + (lane >> 2);
    #pragma unroll
    for (int ks = 0; ks < 16; ks++) {
        int k0 = ks * 8;
        unsigned a[4];
        a[0] = As[r0 * EAST + k0 + (lane & 3)];
        a[1] = As[(r0 + 8) * EAST + k0 + (lane & 3)];
        a[2] = As[r0 * EAST + k0 + 4 + (lane & 3)];
        a[3] = As[(r0 + 8) * EAST + k0 + 4 + (lane & 3)];
        #pragma unroll
        for (int j = 0; j < 8; j++) {
            unsigned b0 = Ws[(k0 + (lane & 3)) * EWST + 8 * j + (lane >> 2)];
            unsigned b1 = Ws[(k0 + 4 + (lane & 3)) * EWST + 8 * j + (lane >> 2)];
            mma8(acc[j], a, b0, b1);
        }
    }
    __syncthreads();
    float* P = (float*)As;
    #pragma unroll
    for (int j = 0; j < 8; j++) {
        int c0 = 8 * j + 2 * (lane & 3);
        float b0v = bp2s[c0], b1v = bp2s[c0 + 1];
        float y;
        y = acc[j].x + b0v; P[r0 * EPST + c0] = y > 0.f ? y : 0.f;
        y = acc[j].y + b1v; P[r0 * EPST + c0 + 1] = y > 0.f ? y : 0.f;
        y = acc[j].z + b0v; P[(r0 + 8) * EPST + c0] = y > 0.f ? y : 0.f;
        y = acc[j].w + b1v; P[(r0 + 8) * EPST + c0 + 1] = y > 0.f ? y : 0.f;
    }
    __syncthreads();
    if (t < 128) {
        int e = e0 + t;
        if (e < E) {
            float a3 = bp3[0];
            #pragma unroll
            for (int c = 0; c < 64; c++) a3 = fmaf(P[t * EPST + c], w3s[c], a3);
            pred[e] = 1.f / (1.f + expf(-a3));
        }
    }
}

// ---------------- launch ----------------
extern "C" void kernel_launch(void* const* d_in, const int* in_sizes, int n_in,
                              void* d_out, int out_size) {
    const float* x   = (const float*)d_in[0];
    const int*   ei  = (const int*)d_in[1];
    const float* W1  = (const float*)d_in[2];
    const float* b1  = (const float*)d_in[3];
    const float* ga1 = (const float*)d_in[4];
    const float* be1 = (const float*)d_in[5];
    const float* W2  = (const float*)d_in[6];
    const float* b2  = (const float*)d_in[7];
    const float* ga2 = (const float*)d_in[8];
    const float* be2 = (const float*)d_in[9];
    const float* Wp1 = (const float*)d_in[10];
    const float* bp1 = (const float*)d_in[11];
    const float* Wp2 = (const float*)d_in[12];
    const float* bp2 = (const float*)d_in[13];
    const float* Wp3 = (const float*)d_in[14];
    const float* bp3 = (const float*)d_in[15];

    int n = in_sizes[0] / NF;
    int E = in_sizes[1] / 2;
    const int* src = ei;
    const int* dst = ei + E;

    float* out  = (float*)d_out;
    float* h2   = out;
    float* pred = out + (size_t)n * C2;
    float nf = (float)n;

    k_zero<<<(n + 255) / 256, 256>>>(n);
    k_hist<<<(E + 255) / 256, 256>>>(dst, E);
    k_scan<<<1, 1024>>>(n);
    k_csr<<<(E + 255) / 256, 256>>>(src, dst, E);
    k_aggx<<<(n * 4 + 255) / 256, 256>>>(x, n);
    k_gcn1<<<(n + 63) / 64, 256>>>(W1, b1, n);
    k_bn1<<<(n * (C1 / 4) + 255) / 256, 256>>>(ga1, be1, nf, n);
    k_agg1<<<(n * 32 + 255) / 256, 256>>>(n);
    k_gcn2<<<(n + 63) / 64, 256>>>(W2, b2, n);
    k_stats2<<<(n + 255) / 256, 256>>>(n);
    k_bnp2<<<1, 256>>>(ga2, be2, nf);
    k_uv<<<(n + 63) / 64, 256>>>(h2, Wp1, bp1, n);

    static int smem_set = 0;
    if (!smem_set) {
        cudaFuncSetAttribute(k_edge, cudaFuncAttributeMaxDynamicSharedMemorySize, 112 * 1024);
        smem_set = 1;
    }
    size_t esm = (size_t)(128 * EAST + 128 * EWST + 128) * 4;
    k_edge<<<(E + 127) / 128, 256, esm>>>(src, dst, Wp2, bp2, Wp3, bp3, pred, E);
}